// round 5
// baseline (speedup 1.0000x reference)
#include <cuda_runtime.h>

#define N_NODES 50000
#define IN_CH   128
#define OUT_CH  64
#define N_EDGES 800000

// Scratch for projected features h = x @ W^T  (50000 x 64 f32 = 12.8 MB)
__device__ float g_h[N_NODES * OUT_CH];

// ---------------------------------------------------------------------------
// Kernel 1: h = x @ W^T   (fp32, W staged in smem as [c][k4] float4 rows)
// Warp layout: lane = row within a 32-row group, channel range warp-uniform:
//   warp w handles rows blk*64 + (w&1)*32 + lane, channels (w>>1)*32 .. +31.
// Every Ws4 load is the SAME address for all 32 lanes -> pure LDS broadcast,
// zero bank conflicts. 782 blocks x 4 warps = 5.3 warps/SMSP.
// ---------------------------------------------------------------------------
__global__ void __launch_bounds__(128) gemm_kernel(
    const float* __restrict__ x,
    const float* __restrict__ W)
{
    __shared__ float4 Ws4[OUT_CH * IN_CH / 4];  // 32 KB: Ws4[c*32 + k4]

    const float4* Wg = reinterpret_cast<const float4*>(W);
    for (int i = threadIdx.x; i < OUT_CH * IN_CH / 4; i += 128)
        Ws4[i] = Wg[i];
    __syncthreads();

    int wid   = threadIdx.x >> 5;
    int lane  = threadIdx.x & 31;
    int row   = blockIdx.x * 64 + (wid & 1) * 32 + lane;
    int cbase = (wid >> 1) * 32;
    if (row >= N_NODES) return;

    float acc[32];
#pragma unroll
    for (int j = 0; j < 32; j++) acc[j] = 0.0f;

    const float4* xr = reinterpret_cast<const float4*>(x + (size_t)row * IN_CH);

#pragma unroll 4
    for (int k4 = 0; k4 < IN_CH / 4; k4++) {
        float4 xv = __ldg(xr + k4);
#pragma unroll
        for (int j = 0; j < 32; j++) {
            float4 w = Ws4[(cbase + j) * (IN_CH / 4) + k4];  // all-lane broadcast
            acc[j] = fmaf(xv.x, w.x, acc[j]);
            acc[j] = fmaf(xv.y, w.y, acc[j]);
            acc[j] = fmaf(xv.z, w.z, acc[j]);
            acc[j] = fmaf(xv.w, w.w, acc[j]);
        }
    }

    float4* hr = reinterpret_cast<float4*>(g_h + (size_t)row * OUT_CH + cbase);
#pragma unroll
    for (int j4 = 0; j4 < 8; j4++)
        hr[j4] = make_float4(acc[4 * j4 + 0], acc[4 * j4 + 1],
                             acc[4 * j4 + 2], acc[4 * j4 + 3]);
}

// ---------------------------------------------------------------------------
// Kernel 2: out[n][c] = bias[c]   — float4 stores (12.8 MB at streaming rate)
// ---------------------------------------------------------------------------
__global__ void __launch_bounds__(256) init_out_kernel(
    const float* __restrict__ bias,
    float* __restrict__ out)
{
    int i = blockIdx.x * blockDim.x + threadIdx.x;     // float4 index
    if (i < N_NODES * OUT_CH / 4) {
        float4 b = __ldg(reinterpret_cast<const float4*>(bias) + (i & 15));
        reinterpret_cast<float4*>(out)[i] = b;
    }
}

// ---------------------------------------------------------------------------
// Kernel 3: out[dst] += h[src]  for every edge.
// 16 threads per edge, float4 gather + red.global.add.v4.f32 (REDG.128).
// edge_index is int32 on device (JAX x64 disabled demotes int64 -> int32).
// ---------------------------------------------------------------------------
__global__ void __launch_bounds__(256) scatter_kernel(
    const int* __restrict__ ei,   // [2, N_EDGES] int32
    float* __restrict__ out)
{
    int t  = blockIdx.x * blockDim.x + threadIdx.x;
    int e  = t >> 4;           // edge id
    int c4 = t & 15;           // which float4 of the 64-ch row
    if (e >= N_EDGES) return;

    int src = __ldg(ei + e);
    int dst = __ldg(ei + N_EDGES + e);

    const float4* hrow = reinterpret_cast<const float4*>(g_h + (size_t)src * OUT_CH);
    float4 v = __ldg(hrow + c4);

    float* o = out + (size_t)dst * OUT_CH + c4 * 4;
    asm volatile("red.global.add.v4.f32 [%0], {%1, %2, %3, %4};"
                 :: "l"(o), "f"(v.x), "f"(v.y), "f"(v.z), "f"(v.w)
                 : "memory");
}

// ---------------------------------------------------------------------------
// Launch
// ---------------------------------------------------------------------------
extern "C" void kernel_launch(void* const* d_in, const int* in_sizes, int n_in,
                              void* d_out, int out_size)
{
    const float* x    = (const float*)d_in[0];      // [50000, 128] f32
    const int*   ei   = (const int*)d_in[1];        // [2, 800000] i32
    const float* W    = (const float*)d_in[2];      // [64, 128] f32
    const float* bias = (const float*)d_in[3];      // [64] f32
    float*       out  = (float*)d_out;              // [50000, 64] f32

    (void)in_sizes; (void)n_in; (void)out_size;

    // out = bias (independent of gemm)
    init_out_kernel<<<(N_NODES * OUT_CH / 4 + 255) / 256, 256>>>(bias, out);

    // h = x @ W^T   (782 blocks x 128 threads; 64 rows x 64 ch per block)
    gemm_kernel<<<(N_NODES + 63) / 64, 128>>>(x, W);

    // out[dst] += h[src]
    int total_threads = N_EDGES * 16;
    scatter_kernel<<<total_threads / 256, 256>>>(ei, out);
}

// round 7
// speedup vs baseline: 1.3341x; 1.3341x over previous
#include <cuda_runtime.h>
#include <cuda_bf16.h>
#include <cstdint>

#define N_NODES 50000
#define IN_CH   128
#define OUT_CH  64
#define N_EDGES 800000

// Scratch for projected features h = x @ W^T  (50000 x 64 f32 = 12.8 MB)
__device__ float g_h[N_NODES * OUT_CH];

// ---------------------------------------------------------------------------
// smem layout (in 32-bit words). Padded strides chosen so every mma fragment
// load is bank-conflict-free:
//   A rows: stride 68 words -> bank(r,cp) = (68r+cp)%32 = (4r+cp), all distinct
//   B kp-rows: stride 72 words -> bank(kp,n) = (8kp+n), all distinct
// ---------------------------------------------------------------------------
#define A_STRIDE 68
#define B_STRIDE 72
#define A_HI 0
#define A_LO (128 * A_STRIDE)                 // 8704
#define B_HI (2 * 128 * A_STRIDE)             // 17408
#define B_LO (2 * 128 * A_STRIDE + 64 * B_STRIDE)  // 22016
#define SMEM_WORDS (2 * 128 * A_STRIDE + 2 * 64 * B_STRIDE)   // 26624
#define SMEM_BYTES (SMEM_WORDS * 4)           // 106496

__device__ __forceinline__ uint32_t pack_bf2(float a, float b) {
    __nv_bfloat162 t = __floats2bfloat162_rn(a, b);  // .x=a (low), .y=b (high)
    return *reinterpret_cast<uint32_t*>(&t);
}

__device__ __forceinline__ void mma_bf16(float* c, const uint32_t* a,
                                         uint32_t b0, uint32_t b1) {
    asm volatile(
        "mma.sync.aligned.m16n8k16.row.col.f32.bf16.bf16.f32 "
        "{%0,%1,%2,%3}, {%4,%5,%6,%7}, {%8,%9}, {%0,%1,%2,%3};"
        : "+f"(c[0]), "+f"(c[1]), "+f"(c[2]), "+f"(c[3])
        : "r"(a[0]), "r"(a[1]), "r"(a[2]), "r"(a[3]), "r"(b0), "r"(b1));
}

// ---------------------------------------------------------------------------
// Kernel 1: h = x @ W^T via HMMA split-bf16 (3-term) emulation.
// CTA: 128 rows x 64 cols x K=128. Warp: 32 rows (2 m-tiles) x 8 n-tiles.
// ---------------------------------------------------------------------------
__global__ void __launch_bounds__(128) gemm_kernel(
    const float* __restrict__ x,
    const float* __restrict__ W)
{
    extern __shared__ uint32_t smw[];

    int tid = threadIdx.x;
    long rowbase = (long)blockIdx.x * 128;

    // --- stage W (64x128) as hi/lo bf16 k-pairs: word[(k/2)*72 + n] ---------
    for (int i = tid * 2; i < OUT_CH * IN_CH; i += 256) {
        int n = i >> 7, k = i & 127;              // k even
        float2 w2 = *reinterpret_cast<const float2*>(W + i);
        float hx = __bfloat162float(__float2bfloat16_rn(w2.x));
        float hy = __bfloat162float(__float2bfloat16_rn(w2.y));
        int wi = (k >> 1) * B_STRIDE + n;
        smw[B_HI + wi] = pack_bf2(hx, hy);
        smw[B_LO + wi] = pack_bf2(w2.x - hx, w2.y - hy);
    }

    // --- stage x tile (128x128) as hi/lo bf16: word[r*68 + k/2] -------------
    for (int i = tid * 2; i < 128 * IN_CH; i += 256) {
        int r = i >> 7, k = i & 127;
        long row = rowbase + r;
        float2 v2 = (row < N_NODES)
                  ? *reinterpret_cast<const float2*>(x + row * IN_CH + k)
                  : make_float2(0.0f, 0.0f);
        float hx = __bfloat162float(__float2bfloat16_rn(v2.x));
        float hy = __bfloat162float(__float2bfloat16_rn(v2.y));
        int wi = r * A_STRIDE + (k >> 1);
        smw[A_HI + wi] = pack_bf2(hx, hy);
        smw[A_LO + wi] = pack_bf2(v2.x - hx, v2.y - hy);
    }
    __syncthreads();

    int wid  = tid >> 5;
    int lane = tid & 31;
    int qr   = lane >> 2;   // group id 0..7
    int qc   = lane & 3;    // thread-in-group 0..3
    int wr   = wid * 32;    // warp row offset in tile

    float acc[2][8][4];
#pragma unroll
    for (int mt = 0; mt < 2; mt++)
#pragma unroll
        for (int nt = 0; nt < 8; nt++)
#pragma unroll
            for (int j = 0; j < 4; j++) acc[mt][nt][j] = 0.0f;

#pragma unroll
    for (int ks = 0; ks < 8; ks++) {
        int kw = ks * 8;  // word offset of this k-step (16 bf16 = 8 words)

        uint32_t ah[2][4], al[2][4];
#pragma unroll
        for (int mt = 0; mt < 2; mt++) {
            int r0 = wr + mt * 16 + qr;
            int i00 = (r0) * A_STRIDE + kw + qc;
            int i10 = (r0 + 8) * A_STRIDE + kw + qc;
            ah[mt][0] = smw[A_HI + i00];
            ah[mt][1] = smw[A_HI + i10];
            ah[mt][2] = smw[A_HI + i00 + 4];
            ah[mt][3] = smw[A_HI + i10 + 4];
            al[mt][0] = smw[A_LO + i00];
            al[mt][1] = smw[A_LO + i10];
            al[mt][2] = smw[A_LO + i00 + 4];
            al[mt][3] = smw[A_LO + i10 + 4];
        }

        int kp0 = ks * 8;
#pragma unroll
        for (int nt = 0; nt < 8; nt++) {
            int n0 = nt * 8 + qr;
            uint32_t bh0 = smw[B_HI + (kp0 + qc) * B_STRIDE + n0];
            uint32_t bh1 = smw[B_HI + (kp0 + qc + 4) * B_STRIDE + n0];
            uint32_t bl0 = smw[B_LO + (kp0 + qc) * B_STRIDE + n0];
            uint32_t bl1 = smw[B_LO + (kp0 + qc + 4) * B_STRIDE + n0];
            mma_bf16(acc[0][nt], ah[0], bh0, bh1);
            mma_bf16(acc[1][nt], ah[1], bh0, bh1);
            mma_bf16(acc[0][nt], ah[0], bl0, bl1);
            mma_bf16(acc[1][nt], ah[1], bl0, bl1);
            mma_bf16(acc[0][nt], al[0], bh0, bh1);
            mma_bf16(acc[1][nt], al[1], bh0, bh1);
        }
    }

    // --- epilogue: c0,c1 -> (qr, 2qc..+1), c2,c3 -> (qr+8, 2qc..+1) ---------
#pragma unroll
    for (int mt = 0; mt < 2; mt++) {
        long r0 = rowbase + wr + mt * 16 + qr;
        long r1 = r0 + 8;
#pragma unroll
        for (int nt = 0; nt < 8; nt++) {
            int col = nt * 8 + qc * 2;
            if (r0 < N_NODES)
                *reinterpret_cast<float2*>(g_h + r0 * OUT_CH + col)
                    = make_float2(acc[mt][nt][0], acc[mt][nt][1]);
            if (r1 < N_NODES)
                *reinterpret_cast<float2*>(g_h + r1 * OUT_CH + col)
                    = make_float2(acc[mt][nt][2], acc[mt][nt][3]);
        }
    }
}

// ---------------------------------------------------------------------------
// Kernel 2: out[n][c] = bias[c]   — float4 stores
// ---------------------------------------------------------------------------
__global__ void __launch_bounds__(256) init_out_kernel(
    const float* __restrict__ bias,
    float* __restrict__ out)
{
    int i = blockIdx.x * blockDim.x + threadIdx.x;     // float4 index
    if (i < N_NODES * OUT_CH / 4) {
        float4 b = __ldg(reinterpret_cast<const float4*>(bias) + (i & 15));
        reinterpret_cast<float4*>(out)[i] = b;
    }
}

// ---------------------------------------------------------------------------
// Kernel 3: out[dst] += h[src] per edge. 16 threads/edge, float4 gather +
// red.global.add.v4.f32. edge_index is int32 on device.
// ---------------------------------------------------------------------------
__global__ void __launch_bounds__(256) scatter_kernel(
    const int* __restrict__ ei,
    float* __restrict__ out)
{
    int t  = blockIdx.x * blockDim.x + threadIdx.x;
    int e  = t >> 4;
    int c4 = t & 15;
    if (e >= N_EDGES) return;

    int src = __ldg(ei + e);
    int dst = __ldg(ei + N_EDGES + e);

    float4 v = __ldg(reinterpret_cast<const float4*>(g_h + (size_t)src * OUT_CH) + c4);
    float* o = out + (size_t)dst * OUT_CH + c4 * 4;
    asm volatile("red.global.add.v4.f32 [%0], {%1, %2, %3, %4};"
                 :: "l"(o), "f"(v.x), "f"(v.y), "f"(v.z), "f"(v.w)
                 : "memory");
}

// ---------------------------------------------------------------------------
// Launch
// ---------------------------------------------------------------------------
extern "C" void kernel_launch(void* const* d_in, const int* in_sizes, int n_in,
                              void* d_out, int out_size)
{
    const float* x    = (const float*)d_in[0];      // [50000, 128] f32
    const int*   ei   = (const int*)d_in[1];        // [2, 800000] i32
    const float* W    = (const float*)d_in[2];      // [64, 128] f32
    const float* bias = (const float*)d_in[3];      // [64] f32
    float*       out  = (float*)d_out;              // [50000, 64] f32

    (void)in_sizes; (void)n_in; (void)out_size;

    static bool attr_set = false;
    if (!attr_set) {
        cudaFuncSetAttribute(gemm_kernel,
                             cudaFuncAttributeMaxDynamicSharedMemorySize,
                             SMEM_BYTES);
        attr_set = true;
    }

    init_out_kernel<<<(N_NODES * OUT_CH / 4 + 255) / 256, 256>>>(bias, out);

    gemm_kernel<<<(N_NODES + 127) / 128, 128, SMEM_BYTES>>>(x, W);

    scatter_kernel<<<(N_EDGES * 16) / 256, 256>>>(ei, out);
}

// round 8
// speedup vs baseline: 1.4202x; 1.0645x over previous
#include <cuda_runtime.h>
#include <cuda_bf16.h>
#include <cstdint>

#define N_NODES 50000
#define IN_CH   128
#define OUT_CH  64
#define N_EDGES 800000

// Scratch for projected features h = x @ W^T  (50000 x 64 f32 = 12.8 MB)
__device__ float g_h[N_NODES * OUT_CH];

// ---------------------------------------------------------------------------
// smem layout (in 32-bit words). Padded strides keep mma fragment loads
// bank-conflict-free:
//   A rows: stride 68 words -> bank(r,cp) = (4r+cp)%32, all distinct
//   B kp-rows: stride 72 words -> bank(kp,n) = (8kp+n)%32, all distinct
// ---------------------------------------------------------------------------
#define A_STRIDE 68
#define B_STRIDE 72
#define A_HI 0
#define A_LO (128 * A_STRIDE)                       // 8704
#define B_HI (2 * 128 * A_STRIDE)                   // 17408
#define B_LO (2 * 128 * A_STRIDE + 64 * B_STRIDE)   // 22016
#define SMEM_WORDS (2 * 128 * A_STRIDE + 2 * 64 * B_STRIDE)   // 26624
#define SMEM_BYTES (SMEM_WORDS * 4)                 // 106496

__device__ __forceinline__ uint32_t pack_bf2(float a, float b) {
    __nv_bfloat162 t = __floats2bfloat162_rn(a, b);
    return *reinterpret_cast<uint32_t*>(&t);
}

__device__ __forceinline__ void mma_bf16(float* c, const uint32_t* a,
                                         uint32_t b0, uint32_t b1) {
    asm volatile(
        "mma.sync.aligned.m16n8k16.row.col.f32.bf16.bf16.f32 "
        "{%0,%1,%2,%3}, {%4,%5,%6,%7}, {%8,%9}, {%0,%1,%2,%3};"
        : "+f"(c[0]), "+f"(c[1]), "+f"(c[2]), "+f"(c[3])
        : "r"(a[0]), "r"(a[1]), "r"(a[2]), "r"(a[3]), "r"(b0), "r"(b1));
}

// ---------------------------------------------------------------------------
// Kernel 1: h = x @ W^T via HMMA split-bf16 (3-term) emulation.
// CTA: 128 rows x 64 cols x K=128; 8 warps, each warp = one 16-row m-tile.
// 2 CTAs/SM co-resident (208 KB smem) -> 4 warps/SMSP for latency hiding.
// ---------------------------------------------------------------------------
__global__ void __launch_bounds__(256, 2) gemm_kernel(
    const float* __restrict__ x,
    const float* __restrict__ W)
{
    extern __shared__ uint32_t smw[];

    int tid = threadIdx.x;
    long rowbase = (long)blockIdx.x * 128;

    // --- stage W (64x128) as hi/lo bf16 k-pairs: word[(k/2)*72 + n] ---------
    for (int i = tid * 2; i < OUT_CH * IN_CH; i += 512) {
        int n = i >> 7, k = i & 127;              // k even
        float2 w2 = *reinterpret_cast<const float2*>(W + i);
        float hx = __bfloat162float(__float2bfloat16_rn(w2.x));
        float hy = __bfloat162float(__float2bfloat16_rn(w2.y));
        int wi = (k >> 1) * B_STRIDE + n;
        smw[B_HI + wi] = pack_bf2(hx, hy);
        smw[B_LO + wi] = pack_bf2(w2.x - hx, w2.y - hy);
    }

    // --- stage x tile (128x128) as hi/lo bf16: word[r*68 + k/2] -------------
    for (int i = tid * 2; i < 128 * IN_CH; i += 512) {
        int r = i >> 7, k = i & 127;
        long row = rowbase + r;
        float2 v2 = (row < N_NODES)
                  ? *reinterpret_cast<const float2*>(x + row * IN_CH + k)
                  : make_float2(0.0f, 0.0f);
        float hx = __bfloat162float(__float2bfloat16_rn(v2.x));
        float hy = __bfloat162float(__float2bfloat16_rn(v2.y));
        int wi = r * A_STRIDE + (k >> 1);
        smw[A_HI + wi] = pack_bf2(hx, hy);
        smw[A_LO + wi] = pack_bf2(v2.x - hx, v2.y - hy);
    }
    __syncthreads();

    int wid  = tid >> 5;
    int lane = tid & 31;
    int qr   = lane >> 2;   // group id 0..7
    int qc   = lane & 3;    // thread-in-group 0..3
    int wr   = wid * 16;    // warp's 16-row m-tile offset

    float acc[8][4];
#pragma unroll
    for (int nt = 0; nt < 8; nt++)
#pragma unroll
        for (int j = 0; j < 4; j++) acc[nt][j] = 0.0f;

#pragma unroll
    for (int ks = 0; ks < 8; ks++) {
        int kw = ks * 8;  // word offset of this k-step (16 bf16 = 8 words)

        uint32_t ah[4], al[4];
        {
            int r0  = wr + qr;
            int i00 = r0 * A_STRIDE + kw + qc;
            int i10 = (r0 + 8) * A_STRIDE + kw + qc;
            ah[0] = smw[A_HI + i00];
            ah[1] = smw[A_HI + i10];
            ah[2] = smw[A_HI + i00 + 4];
            ah[3] = smw[A_HI + i10 + 4];
            al[0] = smw[A_LO + i00];
            al[1] = smw[A_LO + i10];
            al[2] = smw[A_LO + i00 + 4];
            al[3] = smw[A_LO + i10 + 4];
        }

        int kp0 = ks * 8;
#pragma unroll
        for (int nt = 0; nt < 8; nt++) {
            int n0 = nt * 8 + qr;
            uint32_t bh0 = smw[B_HI + (kp0 + qc) * B_STRIDE + n0];
            uint32_t bh1 = smw[B_HI + (kp0 + qc + 4) * B_STRIDE + n0];
            uint32_t bl0 = smw[B_LO + (kp0 + qc) * B_STRIDE + n0];
            uint32_t bl1 = smw[B_LO + (kp0 + qc + 4) * B_STRIDE + n0];
            mma_bf16(acc[nt], ah, bh0, bh1);
            mma_bf16(acc[nt], ah, bl0, bl1);
            mma_bf16(acc[nt], al, bh0, bh1);
        }
    }

    // --- epilogue: c0,c1 -> (qr, 2qc..+1), c2,c3 -> (qr+8, 2qc..+1) ---------
    long r0 = rowbase + wr + qr;
    long r1 = r0 + 8;
#pragma unroll
    for (int nt = 0; nt < 8; nt++) {
        int col = nt * 8 + qc * 2;
        if (r0 < N_NODES)
            *reinterpret_cast<float2*>(g_h + r0 * OUT_CH + col)
                = make_float2(acc[nt][0], acc[nt][1]);
        if (r1 < N_NODES)
            *reinterpret_cast<float2*>(g_h + r1 * OUT_CH + col)
                = make_float2(acc[nt][2], acc[nt][3]);
    }
}

// ---------------------------------------------------------------------------
// Kernel 2: out[n][c] = bias[c]   — float4 stores
// ---------------------------------------------------------------------------
__global__ void __launch_bounds__(256) init_out_kernel(
    const float* __restrict__ bias,
    float* __restrict__ out)
{
    int i = blockIdx.x * blockDim.x + threadIdx.x;     // float4 index
    if (i < N_NODES * OUT_CH / 4) {
        float4 b = __ldg(reinterpret_cast<const float4*>(bias) + (i & 15));
        reinterpret_cast<float4*>(out)[i] = b;
    }
}

// ---------------------------------------------------------------------------
// Kernel 3: out[dst] += h[src] per edge. 16 threads/edge, float4 gather +
// red.global.add.v4.f32. edge_index is int32 on device.
// ---------------------------------------------------------------------------
__global__ void __launch_bounds__(256) scatter_kernel(
    const int* __restrict__ ei,
    float* __restrict__ out)
{
    int t  = blockIdx.x * blockDim.x + threadIdx.x;
    int e  = t >> 4;
    int c4 = t & 15;
    if (e >= N_EDGES) return;

    int src = __ldg(ei + e);
    int dst = __ldg(ei + N_EDGES + e);

    float4 v = __ldg(reinterpret_cast<const float4*>(g_h + (size_t)src * OUT_CH) + c4);
    float* o = out + (size_t)dst * OUT_CH + c4 * 4;
    asm volatile("red.global.add.v4.f32 [%0], {%1, %2, %3, %4};"
                 :: "l"(o), "f"(v.x), "f"(v.y), "f"(v.z), "f"(v.w)
                 : "memory");
}

// ---------------------------------------------------------------------------
// Launch
// ---------------------------------------------------------------------------
extern "C" void kernel_launch(void* const* d_in, const int* in_sizes, int n_in,
                              void* d_out, int out_size)
{
    const float* x    = (const float*)d_in[0];      // [50000, 128] f32
    const int*   ei   = (const int*)d_in[1];        // [2, 800000] i32
    const float* W    = (const float*)d_in[2];      // [64, 128] f32
    const float* bias = (const float*)d_in[3];      // [64] f32
    float*       out  = (float*)d_out;              // [50000, 64] f32

    (void)in_sizes; (void)n_in; (void)out_size;

    static bool attr_set = false;
    if (!attr_set) {
        cudaFuncSetAttribute(gemm_kernel,
                             cudaFuncAttributeMaxDynamicSharedMemorySize,
                             SMEM_BYTES);
        attr_set = true;
    }

    init_out_kernel<<<(N_NODES * OUT_CH / 4 + 255) / 256, 256>>>(bias, out);

    gemm_kernel<<<(N_NODES + 127) / 128, 256, SMEM_BYTES>>>(x, W);

    scatter_kernel<<<(N_EDGES * 16) / 256, 256>>>(ei, out);
}

// round 9
// speedup vs baseline: 1.6819x; 1.1842x over previous
#include <cuda_runtime.h>
#include <cuda_bf16.h>
#include <cstdint>

#define N_NODES 50000
#define IN_CH   128
#define OUT_CH  64
#define N_EDGES 800000
#define CAP     96          // max degree capacity (Poisson(16): P(>96) ~ 1e-40)

// Scratch (device globals — no allocation allowed)
__device__ float g_h[N_NODES * OUT_CH];     // projected features, 12.8 MB
__device__ int   g_cnt[N_NODES];            // per-dst degree counters
__device__ int   g_srcs[N_NODES * CAP];     // bucketed src ids, 19.2 MB

// ---------------------------------------------------------------------------
// smem layout (32-bit words), bank-conflict-free strides (see R7/R8 notes)
// ---------------------------------------------------------------------------
#define A_STRIDE 68
#define B_STRIDE 72
#define A_HI 0
#define A_LO (128 * A_STRIDE)
#define B_HI (2 * 128 * A_STRIDE)
#define B_LO (2 * 128 * A_STRIDE + 64 * B_STRIDE)
#define SMEM_WORDS (2 * 128 * A_STRIDE + 2 * 64 * B_STRIDE)
#define SMEM_BYTES (SMEM_WORDS * 4)          // 106496

__device__ __forceinline__ uint32_t pack_bf2(float a, float b) {
    __nv_bfloat162 t = __floats2bfloat162_rn(a, b);
    return *reinterpret_cast<uint32_t*>(&t);
}

__device__ __forceinline__ void mma_bf16(float* c, const uint32_t* a,
                                         uint32_t b0, uint32_t b1) {
    asm volatile(
        "mma.sync.aligned.m16n8k16.row.col.f32.bf16.bf16.f32 "
        "{%0,%1,%2,%3}, {%4,%5,%6,%7}, {%8,%9}, {%0,%1,%2,%3};"
        : "+f"(c[0]), "+f"(c[1]), "+f"(c[2]), "+f"(c[3])
        : "r"(a[0]), "r"(a[1]), "r"(a[2]), "r"(a[3]), "r"(b0), "r"(b1));
}

// ---------------------------------------------------------------------------
// Kernel 1: h = x @ W^T via HMMA split-bf16 (3-term). Unchanged from R8.
// ---------------------------------------------------------------------------
__global__ void __launch_bounds__(256, 2) gemm_kernel(
    const float* __restrict__ x,
    const float* __restrict__ W)
{
    extern __shared__ uint32_t smw[];

    int tid = threadIdx.x;
    long rowbase = (long)blockIdx.x * 128;

    for (int i = tid * 2; i < OUT_CH * IN_CH; i += 512) {
        int n = i >> 7, k = i & 127;
        float2 w2 = *reinterpret_cast<const float2*>(W + i);
        float hx = __bfloat162float(__float2bfloat16_rn(w2.x));
        float hy = __bfloat162float(__float2bfloat16_rn(w2.y));
        int wi = (k >> 1) * B_STRIDE + n;
        smw[B_HI + wi] = pack_bf2(hx, hy);
        smw[B_LO + wi] = pack_bf2(w2.x - hx, w2.y - hy);
    }

    for (int i = tid * 2; i < 128 * IN_CH; i += 512) {
        int r = i >> 7, k = i & 127;
        long row = rowbase + r;
        float2 v2 = (row < N_NODES)
                  ? *reinterpret_cast<const float2*>(x + row * IN_CH + k)
                  : make_float2(0.0f, 0.0f);
        float hx = __bfloat162float(__float2bfloat16_rn(v2.x));
        float hy = __bfloat162float(__float2bfloat16_rn(v2.y));
        int wi = r * A_STRIDE + (k >> 1);
        smw[A_HI + wi] = pack_bf2(hx, hy);
        smw[A_LO + wi] = pack_bf2(v2.x - hx, v2.y - hy);
    }
    __syncthreads();

    int wid  = tid >> 5;
    int lane = tid & 31;
    int qr   = lane >> 2;
    int qc   = lane & 3;
    int wr   = wid * 16;

    float acc[8][4];
#pragma unroll
    for (int nt = 0; nt < 8; nt++)
#pragma unroll
        for (int j = 0; j < 4; j++) acc[nt][j] = 0.0f;

#pragma unroll
    for (int ks = 0; ks < 8; ks++) {
        int kw = ks * 8;

        uint32_t ah[4], al[4];
        {
            int r0  = wr + qr;
            int i00 = r0 * A_STRIDE + kw + qc;
            int i10 = (r0 + 8) * A_STRIDE + kw + qc;
            ah[0] = smw[A_HI + i00];
            ah[1] = smw[A_HI + i10];
            ah[2] = smw[A_HI + i00 + 4];
            ah[3] = smw[A_HI + i10 + 4];
            al[0] = smw[A_LO + i00];
            al[1] = smw[A_LO + i10];
            al[2] = smw[A_LO + i00 + 4];
            al[3] = smw[A_LO + i10 + 4];
        }

        int kp0 = ks * 8;
#pragma unroll
        for (int nt = 0; nt < 8; nt++) {
            int n0 = nt * 8 + qr;
            uint32_t bh0 = smw[B_HI + (kp0 + qc) * B_STRIDE + n0];
            uint32_t bh1 = smw[B_HI + (kp0 + qc + 4) * B_STRIDE + n0];
            uint32_t bl0 = smw[B_LO + (kp0 + qc) * B_STRIDE + n0];
            uint32_t bl1 = smw[B_LO + (kp0 + qc + 4) * B_STRIDE + n0];
            mma_bf16(acc[nt], ah, bh0, bh1);
            mma_bf16(acc[nt], ah, bl0, bl1);
            mma_bf16(acc[nt], al, bh0, bh1);
        }
    }

    long r0 = rowbase + wr + qr;
    long r1 = r0 + 8;
#pragma unroll
    for (int nt = 0; nt < 8; nt++) {
        int col = nt * 8 + qc * 2;
        if (r0 < N_NODES)
            *reinterpret_cast<float2*>(g_h + r0 * OUT_CH + col)
                = make_float2(acc[nt][0], acc[nt][1]);
        if (r1 < N_NODES)
            *reinterpret_cast<float2*>(g_h + r1 * OUT_CH + col)
                = make_float2(acc[nt][2], acc[nt][3]);
    }
}

// ---------------------------------------------------------------------------
// Kernel 2: zero the degree counters (200 KB)
// ---------------------------------------------------------------------------
__global__ void __launch_bounds__(512) zero_cnt_kernel()
{
    int i = blockIdx.x * 512 + threadIdx.x;
    if (i < N_NODES) g_cnt[i] = 0;
}

// ---------------------------------------------------------------------------
// Kernel 3: bucket fill — g_srcs[dst*CAP + pos] = src (scan-free CSR)
// ---------------------------------------------------------------------------
__global__ void __launch_bounds__(256) fill_kernel(const int* __restrict__ ei)
{
    int e = blockIdx.x * 256 + threadIdx.x;
    if (e >= N_EDGES) return;
    int src = __ldg(ei + e);
    int dst = __ldg(ei + N_EDGES + e);
    int pos = atomicAdd(&g_cnt[dst], 1);
    if (pos < CAP) g_srcs[dst * CAP + pos] = src;
}

// ---------------------------------------------------------------------------
// Kernel 4: out[n] = bias + sum_{e in bucket n} h[src_e]
// 16 threads per node, one float4 (4 ch) each. No atomics, bias fused.
// ---------------------------------------------------------------------------
__global__ void __launch_bounds__(256) aggregate_kernel(
    const float* __restrict__ bias,
    float* __restrict__ out)
{
    int t    = blockIdx.x * 256 + threadIdx.x;
    int node = t >> 4;
    int c4   = t & 15;
    if (node >= N_NODES) return;

    int deg = __ldg(g_cnt + node);
    if (deg > CAP) deg = CAP;
    const int* bucket = g_srcs + node * CAP;

    float4 acc = __ldg(reinterpret_cast<const float4*>(bias) + c4);

    int e = 0;
    for (; e + 1 < deg; e += 2) {
        int s0 = __ldg(bucket + e);
        int s1 = __ldg(bucket + e + 1);
        float4 v0 = __ldg(reinterpret_cast<const float4*>(g_h + (size_t)s0 * OUT_CH) + c4);
        float4 v1 = __ldg(reinterpret_cast<const float4*>(g_h + (size_t)s1 * OUT_CH) + c4);
        acc.x += v0.x + v1.x;
        acc.y += v0.y + v1.y;
        acc.z += v0.z + v1.z;
        acc.w += v0.w + v1.w;
    }
    if (e < deg) {
        int s0 = __ldg(bucket + e);
        float4 v0 = __ldg(reinterpret_cast<const float4*>(g_h + (size_t)s0 * OUT_CH) + c4);
        acc.x += v0.x; acc.y += v0.y; acc.z += v0.z; acc.w += v0.w;
    }

    reinterpret_cast<float4*>(out + (size_t)node * OUT_CH)[c4] = acc;
}

// ---------------------------------------------------------------------------
// Launch
// ---------------------------------------------------------------------------
extern "C" void kernel_launch(void* const* d_in, const int* in_sizes, int n_in,
                              void* d_out, int out_size)
{
    const float* x    = (const float*)d_in[0];      // [50000, 128] f32
    const int*   ei   = (const int*)d_in[1];        // [2, 800000] i32
    const float* W    = (const float*)d_in[2];      // [64, 128] f32
    const float* bias = (const float*)d_in[3];      // [64] f32
    float*       out  = (float*)d_out;              // [50000, 64] f32

    (void)in_sizes; (void)n_in; (void)out_size;

    static bool attr_set = false;
    if (!attr_set) {
        cudaFuncSetAttribute(gemm_kernel,
                             cudaFuncAttributeMaxDynamicSharedMemorySize,
                             SMEM_BYTES);
        attr_set = true;
    }

    zero_cnt_kernel<<<(N_NODES + 511) / 512, 512>>>();
    fill_kernel<<<(N_EDGES + 255) / 256, 256>>>(ei);

    gemm_kernel<<<(N_NODES + 127) / 128, 256, SMEM_BYTES>>>(x, W);

    aggregate_kernel<<<(N_NODES * 16 + 255) / 256, 256>>>(bias, out);
}

// round 10
// speedup vs baseline: 1.7579x; 1.0452x over previous
#include <cuda_runtime.h>
#include <cuda_bf16.h>
#include <cstdint>

#define N_NODES 50000
#define IN_CH   128
#define OUT_CH  64
#define N_EDGES 800000
#define CAP     96          // max degree capacity (Poisson(16): P(>96) ~ 1e-40)

// Scratch (device globals — no allocation allowed)
__device__ float g_h[N_NODES * OUT_CH];     // projected features, 12.8 MB
__device__ int   g_cnt[N_NODES];            // per-dst degree counters
__device__ int   g_srcs[N_NODES * CAP];     // bucketed src ids, 19.2 MB

// ---------------------------------------------------------------------------
// smem layout (32-bit words), bank-conflict-free strides (see R7/R8 notes)
// ---------------------------------------------------------------------------
#define A_STRIDE 68
#define B_STRIDE 72
#define A_HI 0
#define A_LO (128 * A_STRIDE)
#define B_HI (2 * 128 * A_STRIDE)
#define B_LO (2 * 128 * A_STRIDE + 64 * B_STRIDE)
#define SMEM_WORDS (2 * 128 * A_STRIDE + 2 * 64 * B_STRIDE)
#define SMEM_BYTES (SMEM_WORDS * 4)          // 106496

__device__ __forceinline__ uint32_t pack_bf2(float a, float b) {
    __nv_bfloat162 t = __floats2bfloat162_rn(a, b);
    return *reinterpret_cast<uint32_t*>(&t);
}

__device__ __forceinline__ void mma_bf16(float* c, const uint32_t* a,
                                         uint32_t b0, uint32_t b1) {
    asm volatile(
        "mma.sync.aligned.m16n8k16.row.col.f32.bf16.bf16.f32 "
        "{%0,%1,%2,%3}, {%4,%5,%6,%7}, {%8,%9}, {%0,%1,%2,%3};"
        : "+f"(c[0]), "+f"(c[1]), "+f"(c[2]), "+f"(c[3])
        : "r"(a[0]), "r"(a[1]), "r"(a[2]), "r"(a[3]), "r"(b0), "r"(b1));
}

// Convert one float4 (4 consecutive k at row r) into hi/lo bf16x2 pairs and
// store at word index wi, wi+stride_kp (pairs (k,k+1) and (k+2,k+3)).
__device__ __forceinline__ void cvt_store4(uint32_t* smw, int hi_base, int lo_base,
                                           int wi, int stride_kp, float4 v) {
    float hx = __bfloat162float(__float2bfloat16_rn(v.x));
    float hy = __bfloat162float(__float2bfloat16_rn(v.y));
    float hz = __bfloat162float(__float2bfloat16_rn(v.z));
    float hw = __bfloat162float(__float2bfloat16_rn(v.w));
    smw[hi_base + wi]             = pack_bf2(hx, hy);
    smw[hi_base + wi + stride_kp] = pack_bf2(hz, hw);
    smw[lo_base + wi]             = pack_bf2(v.x - hx, v.y - hy);
    smw[lo_base + wi + stride_kp] = pack_bf2(v.z - hz, v.w - hw);
}

// ---------------------------------------------------------------------------
// Kernel 1: h = x @ W^T via HMMA split-bf16 (3-term).
// Staging now two-phase (batch-8 LDG.128 then convert+STS) for MLP=8.
// ---------------------------------------------------------------------------
__global__ void __launch_bounds__(256, 2) gemm_kernel(
    const float* __restrict__ x,
    const float* __restrict__ W)
{
    extern __shared__ uint32_t smw[];

    int tid = threadIdx.x;
    long rowbase = (long)blockIdx.x * 128;

    // --- stage W (64x128 = 2048 float4): 8 float4/thread, batched -----------
    {
        float4 wb[8];
        const float4* W4 = reinterpret_cast<const float4*>(W);
#pragma unroll
        for (int j = 0; j < 8; j++)
            wb[j] = __ldg(W4 + tid + j * 256);
#pragma unroll
        for (int j = 0; j < 8; j++) {
            int i = (tid + j * 256) * 4;          // flat float index, k%4==0
            int n = i >> 7, k = i & 127;
            int wi = (k >> 1) * B_STRIDE + n;
            cvt_store4(smw, B_HI, B_LO, wi, B_STRIDE, wb[j]);
        }
    }

    // --- stage x tile (128x128 = 4096 float4): 2 batches of 8/thread --------
    const float4* x4 = reinterpret_cast<const float4*>(x);
#pragma unroll
    for (int b = 0; b < 2; b++) {
        float4 xb[8];
#pragma unroll
        for (int j = 0; j < 8; j++) {
            int idx4 = tid + (b * 8 + j) * 256;   // float4 index within tile
            long row = rowbase + (idx4 >> 5);     // r = (4*idx4)>>7
            xb[j] = (row < N_NODES)
                  ? __ldg(x4 + (size_t)blockIdx.x * 4096 + idx4)
                  : make_float4(0.0f, 0.0f, 0.0f, 0.0f);
        }
#pragma unroll
        for (int j = 0; j < 8; j++) {
            int idx4 = tid + (b * 8 + j) * 256;
            int r = idx4 >> 5;
            int k = (idx4 * 4) & 127;
            int wi = r * A_STRIDE + (k >> 1);
            cvt_store4(smw, A_HI, A_LO, wi, 1, xb[j]);
        }
    }
    __syncthreads();

    int wid  = tid >> 5;
    int lane = tid & 31;
    int qr   = lane >> 2;
    int qc   = lane & 3;
    int wr   = wid * 16;

    float acc[8][4];
#pragma unroll
    for (int nt = 0; nt < 8; nt++)
#pragma unroll
        for (int j = 0; j < 4; j++) acc[nt][j] = 0.0f;

#pragma unroll
    for (int ks = 0; ks < 8; ks++) {
        int kw = ks * 8;

        uint32_t ah[4], al[4];
        {
            int r0  = wr + qr;
            int i00 = r0 * A_STRIDE + kw + qc;
            int i10 = (r0 + 8) * A_STRIDE + kw + qc;
            ah[0] = smw[A_HI + i00];
            ah[1] = smw[A_HI + i10];
            ah[2] = smw[A_HI + i00 + 4];
            ah[3] = smw[A_HI + i10 + 4];
            al[0] = smw[A_LO + i00];
            al[1] = smw[A_LO + i10];
            al[2] = smw[A_LO + i00 + 4];
            al[3] = smw[A_LO + i10 + 4];
        }

        int kp0 = ks * 8;
#pragma unroll
        for (int nt = 0; nt < 8; nt++) {
            int n0 = nt * 8 + qr;
            uint32_t bh0 = smw[B_HI + (kp0 + qc) * B_STRIDE + n0];
            uint32_t bh1 = smw[B_HI + (kp0 + qc + 4) * B_STRIDE + n0];
            uint32_t bl0 = smw[B_LO + (kp0 + qc) * B_STRIDE + n0];
            uint32_t bl1 = smw[B_LO + (kp0 + qc + 4) * B_STRIDE + n0];
            mma_bf16(acc[nt], ah, bh0, bh1);
            mma_bf16(acc[nt], ah, bl0, bl1);
            mma_bf16(acc[nt], al, bh0, bh1);
        }
    }

    long r0 = rowbase + wr + qr;
    long r1 = r0 + 8;
#pragma unroll
    for (int nt = 0; nt < 8; nt++) {
        int col = nt * 8 + qc * 2;
        if (r0 < N_NODES)
            *reinterpret_cast<float2*>(g_h + r0 * OUT_CH + col)
                = make_float2(acc[nt][0], acc[nt][1]);
        if (r1 < N_NODES)
            *reinterpret_cast<float2*>(g_h + r1 * OUT_CH + col)
                = make_float2(acc[nt][2], acc[nt][3]);
    }
}

// ---------------------------------------------------------------------------
// Kernel 2: bucket fill — g_srcs[dst*CAP + pos] = src (scan-free CSR)
// ---------------------------------------------------------------------------
__global__ void __launch_bounds__(256) fill_kernel(const int* __restrict__ ei)
{
    int e = blockIdx.x * 256 + threadIdx.x;
    if (e >= N_EDGES) return;
    int src = __ldg(ei + e);
    int dst = __ldg(ei + N_EDGES + e);
    int pos = atomicAdd(&g_cnt[dst], 1);
    if (pos < CAP) g_srcs[dst * CAP + pos] = src;
}

// ---------------------------------------------------------------------------
// Kernel 3: out[n] = bias + sum_{e in bucket n} h[src_e]
// 16 threads per node, one float4 (4 ch) each. 4-wide gather unroll.
// ---------------------------------------------------------------------------
__global__ void __launch_bounds__(256) aggregate_kernel(
    const float* __restrict__ bias,
    float* __restrict__ out)
{
    int t    = blockIdx.x * 256 + threadIdx.x;
    int node = t >> 4;
    int c4   = t & 15;
    if (node >= N_NODES) return;

    int deg = __ldg(g_cnt + node);
    if (deg > CAP) deg = CAP;
    const int* bucket = g_srcs + node * CAP;

    float4 acc = __ldg(reinterpret_cast<const float4*>(bias) + c4);

    int e = 0;
    for (; e + 3 < deg; e += 4) {
        int s0 = __ldg(bucket + e);
        int s1 = __ldg(bucket + e + 1);
        int s2 = __ldg(bucket + e + 2);
        int s3 = __ldg(bucket + e + 3);
        float4 v0 = __ldg(reinterpret_cast<const float4*>(g_h + (size_t)s0 * OUT_CH) + c4);
        float4 v1 = __ldg(reinterpret_cast<const float4*>(g_h + (size_t)s1 * OUT_CH) + c4);
        float4 v2 = __ldg(reinterpret_cast<const float4*>(g_h + (size_t)s2 * OUT_CH) + c4);
        float4 v3 = __ldg(reinterpret_cast<const float4*>(g_h + (size_t)s3 * OUT_CH) + c4);
        acc.x += (v0.x + v1.x) + (v2.x + v3.x);
        acc.y += (v0.y + v1.y) + (v2.y + v3.y);
        acc.z += (v0.z + v1.z) + (v2.z + v3.z);
        acc.w += (v0.w + v1.w) + (v2.w + v3.w);
    }
    for (; e < deg; e++) {
        int s0 = __ldg(bucket + e);
        float4 v0 = __ldg(reinterpret_cast<const float4*>(g_h + (size_t)s0 * OUT_CH) + c4);
        acc.x += v0.x; acc.y += v0.y; acc.z += v0.z; acc.w += v0.w;
    }

    reinterpret_cast<float4*>(out + (size_t)node * OUT_CH)[c4] = acc;
}

// ---------------------------------------------------------------------------
// Launch
// ---------------------------------------------------------------------------
extern "C" void kernel_launch(void* const* d_in, const int* in_sizes, int n_in,
                              void* d_out, int out_size)
{
    const float* x    = (const float*)d_in[0];      // [50000, 128] f32
    const int*   ei   = (const int*)d_in[1];        // [2, 800000] i32
    const float* W    = (const float*)d_in[2];      // [64, 128] f32
    const float* bias = (const float*)d_in[3];      // [64] f32
    float*       out  = (float*)d_out;              // [50000, 64] f32

    (void)in_sizes; (void)n_in; (void)out_size;

    static void* cnt_addr = nullptr;
    if (!cnt_addr) {
        cudaFuncSetAttribute(gemm_kernel,
                             cudaFuncAttributeMaxDynamicSharedMemorySize,
                             SMEM_BYTES);
        cudaGetSymbolAddress(&cnt_addr, g_cnt);
    }

    // zero degree counters (memset node, replaces a kernel)
    cudaMemsetAsync(cnt_addr, 0, N_NODES * sizeof(int));

    fill_kernel<<<(N_EDGES + 255) / 256, 256>>>(ei);

    gemm_kernel<<<(N_NODES + 127) / 128, 256, SMEM_BYTES>>>(x, W);

    aggregate_kernel<<<(N_NODES * 16 + 255) / 256, 256>>>(bias, out);
}